// round 9
// baseline (speedup 1.0000x reference)
#include <cuda_runtime.h>
#include <math.h>

#define N_NODES 50000
#define N_EDGES 800000
#define NUM_RELS 16
#define H_DIM 128
#define LIN_DIM 512

#define CAP1 256
#define CAP2 2048
#define CAPE1 512
#define CAPE2 4096
#define ESTG  2048          // smem staging cap for E2 list
#define S1LIST 32           // smem S1 list-compare cap

#define BM_WORDS ((N_NODES + 31) / 32)   // 1563

#define NB 444              // 3 blocks/SM on 148 SMs
#define NT 512
#define NQ (N_EDGES / 4)    // 200000 int4 quads
#define QPB ((NQ + NB - 1) / NB)   // 451 quads per block (contiguous slice)

// -------- scratch (device globals, zero-init is the valid empty state) --------
// slot encoding: 0 = absent, otherwise slot+1
__device__ int          g_slot1[N_NODES];
__device__ int          g_slot2[N_NODES];
__device__ unsigned int g_bm1[BM_WORDS + 1];
__device__ unsigned int g_bm2[BM_WORDS + 1];
__device__ int   g_n1, g_n2, g_ne1, g_ne2;
__device__ int   g_s1_nodes[CAP1];
__device__ int   g_s2_nodes[CAP2];
__device__ int   g_e1_src[CAPE1];
__device__ int   g_e2_src[CAPE2];
__device__ int   g_e2_dslot[CAPE2];          // 0-based slot1 of dst
__device__ float g_S[CAP2 * NUM_RELS];       // per-(S2-slot, rel) scalar sums
__device__ float g_msg1[CAP2 * H_DIM];
__device__ float g_root[H_DIM];              // zeroed in phase 1 of each launch

// persistent-generation grid barrier (state persists across graph replays)
__device__ unsigned g_bar_cnt;
__device__ unsigned g_bar_gen;

// ---- release/acquire primitives ----
__device__ __forceinline__ unsigned atom_add_release_gpu(unsigned* p, unsigned v) {
    unsigned old;
    asm volatile("atom.add.release.gpu.u32 %0, [%1], %2;"
                 : "=r"(old) : "l"(p), "r"(v) : "memory");
    return old;
}
__device__ __forceinline__ unsigned ld_acquire_gpu(unsigned* p) {
    unsigned v;
    asm volatile("ld.acquire.gpu.u32 %0, [%1];" : "=r"(v) : "l"(p) : "memory");
    return v;
}
__device__ __forceinline__ void st_release_gpu(unsigned* p, unsigned v) {
    asm volatile("st.release.gpu.u32 [%0], %1;" :: "l"(p), "r"(v) : "memory");
}

#define GRID_SYNC()                                                          \
    do {                                                                     \
        __syncthreads();                                                     \
        if (threadIdx.x == 0) {                                              \
            if (atom_add_release_gpu(&g_bar_cnt, 1u) == (unsigned)(NB - 1)) {\
                *(volatile unsigned*)&g_bar_cnt = 0u;                        \
                st_release_gpu(&g_bar_gen, my_gen + 1u);                     \
            } else {                                                         \
                int spin = 0;                                                \
                while (ld_acquire_gpu(&g_bar_gen) == my_gen)                 \
                    if (++spin > 64) __nanosleep(32);                        \
            }                                                                \
            my_gen++;                                                        \
        }                                                                    \
        __syncthreads();                                                     \
    } while (0)

__device__ __forceinline__ float warp_max_f(float v) {
#pragma unroll
    for (int o = 16; o > 0; o >>= 1) v = fmaxf(v, __shfl_down_sync(0xffffffffu, v, o));
    return v;
}
__device__ __forceinline__ float warp_sum_f(float v) {
#pragma unroll
    for (int o = 16; o > 0; o >>= 1) v += __shfl_down_sync(0xffffffffu, v, o);
    return v;
}

__global__ void __launch_bounds__(NT, 3) k_fused(
    const int* __restrict__ cls, const float* __restrict__ norm,
    const int* __restrict__ src, const int* __restrict__ dst,
    const float* __restrict__ W0, const float* __restrict__ W1,
    const float* __restrict__ W2,
    const float* __restrict__ a1_w, const float* __restrict__ a1_b,
    const float* __restrict__ a2_w, const float* __restrict__ a2_b,
    const float* __restrict__ c1_w, const float* __restrict__ c1_b,
    const float* __restrict__ c2_w, const float* __restrict__ c2_b,
    float* __restrict__ out, int out_size)
{
    const int tx   = threadIdx.x;
    const int bid  = blockIdx.x;

    // this block's contiguous quad slice
    const int q0     = bid * QPB;
    const int nq_blk = (NQ - q0 < QPB) ? (NQ - q0) : QPB;
    const bool own   = (tx < nq_blk);
    const int qi     = q0 + tx;

    unsigned my_gen = 0;
    if (tx == 0) my_gen = ld_acquire_gpu(&g_bar_gen);

    // scan-state (phases 1-3) unioned with phase-5 staging (disjoint in time)
    __shared__ union {
        struct { int4 dst4[QPB + 1]; unsigned bm2s[BM_WORDS + 1]; } scan;
        struct { int dsl[ESTG]; int ssl[ESTG]; } e2;
    } shu;
    __shared__ int   sh_s1[S1LIST];
    __shared__ int   sh_e1[CAPE1];
    __shared__ float sh_h[H_DIM];
    __shared__ float sh_p[NT];
    __shared__ float s_hid[LIN_DIM];
    __shared__ float s_mx, s_sum;

    // ---------- phase 1: load slice -> SMEM; dst == 0 -> S1 / E1 ----------
    if (bid == 0 && tx < H_DIM) g_root[tx] = 0.f;   // zero-before-accumulate (phase 5)
    if (own) {
        const int4 d4 = reinterpret_cast<const int4*>(dst)[qi];
        shu.scan.dst4[tx] = d4;
        int dv[4] = {d4.x, d4.y, d4.z, d4.w};
#pragma unroll
        for (int k = 0; k < 4; k++) {
            if (dv[k] == 0) {
                int s = src[4 * qi + k];
                int p = atomicAdd(&g_ne1, 1);
                if (p < CAPE1) g_e1_src[p] = s;
                if (atomicCAS(&g_slot1[s], 0, -1) == 0) {
                    int sl = atomicAdd(&g_n1, 1);
                    if (sl < CAP1) g_s1_nodes[sl] = s;
                    g_slot1[s] = sl + 1;
                    atomicOr(&g_bm1[s >> 5], 1u << (s & 31));
                }
            }
        }
    }
    GRID_SYNC();

    // ---------- phase 2: dst in S1 -> S2 / E2 (SMEM list compare) ----------
    {
        int n1v = *(volatile int*)&g_n1; if (n1v > CAP1) n1v = CAP1;
        if (tx < S1LIST) sh_s1[tx] = (tx < n1v) ? g_s1_nodes[tx] : -1234567;
        __syncthreads();
        if (own) {
            const int4 d4 = shu.scan.dst4[tx];
            int dv[4] = {d4.x, d4.y, d4.z, d4.w};
            if (n1v <= S1LIST) {
                // pure ALU/LDS membership: slot = index in list
#pragma unroll
                for (int k = 0; k < 4; k++) {
                    int d = dv[k];
                    for (int i = 0; i < n1v; i++) {
                        if (d == sh_s1[i]) {
                            int s = src[4 * qi + k];
                            int p = atomicAdd(&g_ne2, 1);
                            if (p < CAPE2) { g_e2_src[p] = s; g_e2_dslot[p] = i; }
                            if (atomicCAS(&g_slot2[s], 0, -1) == 0) {
                                int q = atomicAdd(&g_n2, 1);
                                if (q < CAP2) g_s2_nodes[q] = s;
                                g_slot2[s] = q + 1;
                                atomicOr(&g_bm2[s >> 5], 1u << (s & 31));
                            }
                            break;
                        }
                    }
                }
            } else {
                // fallback: bitmap path
#pragma unroll
                for (int k = 0; k < 4; k++) {
                    int d = dv[k];
                    if (g_bm1[d >> 5] & (1u << (d & 31))) {
                        int sl = g_slot1[d] - 1;
                        if (sl >= 0 && sl < CAP1) {
                            int s = src[4 * qi + k];
                            int p = atomicAdd(&g_ne2, 1);
                            if (p < CAPE2) { g_e2_src[p] = s; g_e2_dslot[p] = sl; }
                            if (atomicCAS(&g_slot2[s], 0, -1) == 0) {
                                int q = atomicAdd(&g_n2, 1);
                                if (q < CAP2) g_s2_nodes[q] = s;
                                g_slot2[s] = q + 1;
                                atomicOr(&g_bm2[s >> 5], 1u << (s & 31));
                            }
                        }
                    }
                }
            }
        }
    }
    GRID_SYNC();

    // ---------- phase 3: dst in S2 (SMEM bitmap) -> S[slot][cls[src]] += norm[src] ----------
    {
        for (int i = tx; i <= BM_WORDS; i += NT) shu.scan.bm2s[i] = g_bm2[i];
        __syncthreads();
        if (own) {
            const int4 d4 = shu.scan.dst4[tx];
            int dv[4] = {d4.x, d4.y, d4.z, d4.w};
#pragma unroll
            for (int k = 0; k < 4; k++) {
                int d = dv[k];
                if (shu.scan.bm2s[d >> 5] & (1u << (d & 31))) {
                    int sl = g_slot2[d] - 1;
                    if (sl >= 0 && sl < CAP2) {
                        int s = src[4 * qi + k];
                        atomicAdd(&g_S[sl * NUM_RELS + cls[s]], norm[s]);
                    }
                }
            }
        }
    }
    GRID_SYNC();

    // ---------- phase 4: msg1 for S2 nodes ----------
    // h1 = relu(S[sl] . T0) where T0[r][j] = W0[r][r][j]; msg1 = (h1 @ W1[c]) * nm
    {
        int n2v = *(volatile int*)&g_n2; if (n2v > CAP2) n2v = CAP2;
        const int j = tx & 127, q = tx >> 7;
        for (int sl = bid; sl < n2v; sl += NB) {
            if (tx < H_DIM) {
                const float* Sv = &g_S[sl * NUM_RELS];
                float h = 0.f;
#pragma unroll
                for (int r = 0; r < NUM_RELS; r++)
                    h = fmaf(Sv[r], W0[(r * NUM_RELS + r) * H_DIM + tx], h);
                sh_h[tx] = fmaxf(h, 0.f);
            }
            __syncthreads();
            int node = g_s2_nodes[sl];
            int c = cls[node];
            float nm = norm[node];
            const float* Wc = W1 + c * H_DIM * H_DIM;
            float p = 0.f;
#pragma unroll
            for (int kk = 0; kk < 32; kk++) {
                int k = q * 32 + kk;
                p = fmaf(sh_h[k], Wc[k * H_DIM + j], p);
            }
            sh_p[tx] = p;
            __syncthreads();
            if (tx < H_DIM)
                g_msg1[sl * H_DIM + tx] =
                    (sh_p[tx] + sh_p[tx + 128] + sh_p[tx + 256] + sh_p[tx + 384]) * nm;
            __syncthreads();
        }
    }
    GRID_SYNC();

    // ---------- phase 5: msg2 for S1 nodes + root accumulation ----------
    {
        int n1v = *(volatile int*)&g_n1;  if (n1v > CAP1)  n1v = CAP1;
        int ne2 = *(volatile int*)&g_ne2; if (ne2 > CAPE2) ne2 = CAPE2;
        int ne1 = *(volatile int*)&g_ne1; if (ne1 > CAPE1) ne1 = CAPE1;
        if (bid < n1v) {
            int nst = ne2 < ESTG ? ne2 : ESTG;
            for (int e = tx; e < nst; e += NT) {
                shu.e2.dsl[e] = g_e2_dslot[e];
                shu.e2.ssl[e] = g_slot2[g_e2_src[e]] - 1;
            }
            for (int i = tx; i < ne1; i += NT) sh_e1[i] = g_e1_src[i];
            __syncthreads();
            const int j = tx & 127, q = tx >> 7;
            for (int sl = bid; sl < n1v; sl += NB) {
                if (tx < H_DIM) {
                    float acc = 0.f;
                    for (int e = 0; e < nst; e++) {
                        if (shu.e2.dsl[e] == sl) {
                            int ssl = shu.e2.ssl[e];
                            if (ssl >= 0 && ssl < CAP2) acc += g_msg1[ssl * H_DIM + tx];
                        }
                    }
                    for (int e = nst; e < ne2; e++) {   // overflow fallback
                        if (g_e2_dslot[e] == sl) {
                            int ssl = g_slot2[g_e2_src[e]] - 1;
                            if (ssl >= 0 && ssl < CAP2) acc += g_msg1[ssl * H_DIM + tx];
                        }
                    }
                    sh_h[tx] = fmaxf(acc, 0.f);
                }
                __syncthreads();
                int node = g_s1_nodes[sl];
                int c = cls[node];
                float nm = norm[node];
                const float* Wc = W2 + c * H_DIM * H_DIM;
                float p = 0.f;
#pragma unroll
                for (int kk = 0; kk < 32; kk++) {
                    int k = q * 32 + kk;
                    p = fmaf(sh_h[k], Wc[k * H_DIM + j], p);
                }
                sh_p[tx] = p;
                __syncthreads();
                if (tx < H_DIM) {
                    float a = (sh_p[tx] + sh_p[tx + 128] + sh_p[tx + 256] + sh_p[tx + 384]) * nm;
                    int mult = 0;
                    for (int i = 0; i < ne1; i++) mult += (sh_e1[i] == node);
                    if (mult > 0) atomicAdd(&g_root[tx], a * (float)mult);
                }
                __syncthreads();
            }
        }
    }

    // ---------- last barrier: arrive (release); only blocks 0..3 wait ----------
    __syncthreads();
    if (tx == 0) {
        if (atom_add_release_gpu(&g_bar_cnt, 1u) == (unsigned)(NB - 1)) {
            *(volatile unsigned*)&g_bar_cnt = 0u;
            st_release_gpu(&g_bar_gen, my_gen + 1u);
        } else if (bid < 4) {
            int spin = 0;
            while (ld_acquire_gpu(&g_bar_gen) == my_gen)
                if (++spin > 64) __nanosleep(32);
        }
        my_gen++;
    }
    __syncthreads();
    if (bid >= 4) return;

    // ---------- epilogue: blocks 2/3 clean state; blocks 0/1 do heads ----------
    if (bid == 2) {
        int n1v = g_n1; if (n1v > CAP1) n1v = CAP1;
        for (int i = tx; i < n1v; i += NT) {
            int s = g_s1_nodes[i];
            g_slot1[s] = 0;
            g_bm1[s >> 5] = 0u;
        }
        __syncthreads();
        if (tx == 0) { g_n1 = 0; g_ne1 = 0; }
        return;
    }
    if (bid == 3) {
        int n2v = g_n2; if (n2v > CAP2) n2v = CAP2;
        for (int i = tx; i < n2v * NUM_RELS; i += NT) g_S[i] = 0.f;
        for (int i = tx; i < n2v; i += NT) {
            int s = g_s2_nodes[i];
            g_slot2[s] = 0;
            g_bm2[s >> 5] = 0u;
        }
        __syncthreads();
        if (tx == 0) { g_n2 = 0; g_ne2 = 0; }
        return;
    }

    // blocks 0 and 1: each computes softmax(root) locally (g_root NOT modified
    // here; it is zeroed at the start of the next launch, before phase 5).
    {
        const int t = tx;
        const int lane = t & 31;
        const int wid  = t >> 5;
        if (t < H_DIM) sh_h[t] = g_root[t];
        __syncthreads();
        if (wid == 0) {
            float m = fmaxf(fmaxf(sh_h[lane], sh_h[lane + 32]),
                            fmaxf(sh_h[lane + 64], sh_h[lane + 96]));
            m = warp_max_f(m);
            if (lane == 0) s_mx = m;
        }
        __syncthreads();
        if (t < H_DIM) sh_h[t] = expf(sh_h[t] - s_mx);
        __syncthreads();
        if (wid == 0) {
            float sm = sh_h[lane] + sh_h[lane + 32] + sh_h[lane + 64] + sh_h[lane + 96];
            sm = warp_sum_f(sm);
            if (lane == 0) s_sum = sm;
        }
        __syncthreads();
        if (t < H_DIM) sh_h[t] *= (1.f / s_sum);    // root feats
        __syncthreads();

        if (bid == 0) {
            // actor: 128 -> 512 relu -> 128
            {
                float a = a1_b[t];
#pragma unroll 8
                for (int k = 0; k < H_DIM; k++) a = fmaf(sh_h[k], a1_w[k * LIN_DIM + t], a);
                s_hid[t] = fmaxf(a, 0.f);
            }
            __syncthreads();
            {
                int q = t >> 7, j = t & 127;
                const int k0 = q * 128;
                float p = 0.f;
#pragma unroll 8
                for (int k = 0; k < 128; k++)
                    p = fmaf(s_hid[k0 + k], a2_w[(k0 + k) * H_DIM + j], p);
                sh_p[t] = p;
            }
            __syncthreads();
            if (t < H_DIM)
                out[t] = a2_b[t] + sh_p[t] + sh_p[t + 128] + sh_p[t + 256] + sh_p[t + 384];
        } else {
            // critic: 128 -> 512 relu -> 1
            {
                float a = c1_b[t];
#pragma unroll 8
                for (int k = 0; k < H_DIM; k++) a = fmaf(sh_h[k], c1_w[k * LIN_DIM + t], a);
                s_hid[t] = fmaxf(a, 0.f);
            }
            __syncthreads();
            {
                float p = warp_sum_f(s_hid[t] * c2_w[t]);
                if (lane == 0) sh_p[wid] = p;
            }
            __syncthreads();
            if (t == 0) {
                float a = c2_b[0];
#pragma unroll
                for (int i = 0; i < 16; i++) a += sh_p[i];
                if (out_size > H_DIM) out[H_DIM] = a;
            }
        }
    }
}

// ---------------- launch ----------------
extern "C" void kernel_launch(void* const* d_in, const int* in_sizes, int n_in,
                              void* d_out, int out_size) {
    const int*   cls  = (const int*)  d_in[0];
    const float* norm = (const float*)d_in[1];
    const int*   src  = (const int*)  d_in[2];
    const int*   dst  = (const int*)  d_in[3];
    const float* W0   = (const float*)d_in[4];
    const float* W1   = (const float*)d_in[5];
    const float* W2   = (const float*)d_in[6];
    const float* a1_w = (const float*)d_in[7];
    const float* a1_b = (const float*)d_in[8];
    const float* a2_w = (const float*)d_in[9];
    const float* a2_b = (const float*)d_in[10];
    const float* c1_w = (const float*)d_in[11];
    const float* c1_b = (const float*)d_in[12];
    const float* c2_w = (const float*)d_in[13];
    const float* c2_b = (const float*)d_in[14];
    float* out = (float*)d_out;

    k_fused<<<NB, NT>>>(cls, norm, src, dst, W0, W1, W2,
                        a1_w, a1_b, a2_w, a2_b, c1_w, c1_b, c2_w, c2_b,
                        out, out_size);
}

// round 10
// speedup vs baseline: 1.0888x; 1.0888x over previous
#include <cuda_runtime.h>
#include <math.h>

#define N_NODES 50000
#define N_EDGES 800000
#define NUM_RELS 16
#define H_DIM 128
#define LIN_DIM 512

#define CAP1 256
#define CAP2 2048
#define CAPE1 512
#define CAPE2 4096
#define ESTG  2048

#define BM_WORDS ((N_NODES + 31) / 32)   // 1563

#define NB 148                // 1 block/SM -> 148 barrier participants
#define NT 1024               // 32 warps/SM
#define NQ (N_EDGES / 4)      // 200000 int4 quads
#define QPB ((NQ + NB - 1) / NB)    // 1352 quads per block
#define GRP (NT / H_DIM)      // 8 k-groups for GEMV
#define KS  (H_DIM / GRP)     // 16 k's per group

// -------- scratch (device globals, zero-init is the valid empty state) --------
// slot encoding: 0 = absent, otherwise slot+1
__device__ int          g_slot1[N_NODES];
__device__ int          g_slot2[N_NODES];
__device__ unsigned int g_bm1[BM_WORDS + 1];
__device__ unsigned int g_bm2[BM_WORDS + 1];
__device__ int   g_n1, g_n2, g_ne1, g_ne2;
__device__ int   g_s1_nodes[CAP1];
__device__ int   g_s2_nodes[CAP2];
__device__ int   g_e1_src[CAPE1];
__device__ int   g_e2_src[CAPE2];
__device__ int   g_e2_dslot[CAPE2];
__device__ float g_S[CAP2 * NUM_RELS];
__device__ float g_msg1[CAP2 * H_DIM];
__device__ float g_root[H_DIM];            // zeroed in phase 1 of each launch

// persistent-generation grid barrier
__device__ unsigned g_bar_cnt;
__device__ unsigned g_bar_gen;

__device__ __forceinline__ unsigned atom_add_release_gpu(unsigned* p, unsigned v) {
    unsigned old;
    asm volatile("atom.add.release.gpu.u32 %0, [%1], %2;"
                 : "=r"(old) : "l"(p), "r"(v) : "memory");
    return old;
}
__device__ __forceinline__ unsigned ld_acquire_gpu(unsigned* p) {
    unsigned v;
    asm volatile("ld.acquire.gpu.u32 %0, [%1];" : "=r"(v) : "l"(p) : "memory");
    return v;
}
__device__ __forceinline__ void st_release_gpu(unsigned* p, unsigned v) {
    asm volatile("st.release.gpu.u32 [%0], %1;" :: "l"(p), "r"(v) : "memory");
}

#define GRID_SYNC()                                                          \
    do {                                                                     \
        __syncthreads();                                                     \
        if (threadIdx.x == 0) {                                              \
            if (atom_add_release_gpu(&g_bar_cnt, 1u) == (unsigned)(NB - 1)) {\
                *(volatile unsigned*)&g_bar_cnt = 0u;                        \
                st_release_gpu(&g_bar_gen, my_gen + 1u);                     \
            } else {                                                         \
                int spin = 0;                                                \
                while (ld_acquire_gpu(&g_bar_gen) == my_gen)                 \
                    if (++spin > 64) __nanosleep(32);                        \
            }                                                                \
            my_gen++;                                                        \
        }                                                                    \
        __syncthreads();                                                     \
    } while (0)

__device__ __forceinline__ float warp_max_f(float v) {
#pragma unroll
    for (int o = 16; o > 0; o >>= 1) v = fmaxf(v, __shfl_down_sync(0xffffffffu, v, o));
    return v;
}
__device__ __forceinline__ float warp_sum_f(float v) {
#pragma unroll
    for (int o = 16; o > 0; o >>= 1) v += __shfl_down_sync(0xffffffffu, v, o);
    return v;
}

__global__ void __launch_bounds__(NT, 1) k_fused(
    const int* __restrict__ cls, const float* __restrict__ norm,
    const int* __restrict__ src, const int* __restrict__ dst,
    const float* __restrict__ W0, const float* __restrict__ W1,
    const float* __restrict__ W2,
    const float* __restrict__ a1_w, const float* __restrict__ a1_b,
    const float* __restrict__ a2_w, const float* __restrict__ a2_b,
    const float* __restrict__ c1_w, const float* __restrict__ c1_b,
    const float* __restrict__ c2_w, const float* __restrict__ c2_b,
    float* __restrict__ out, int out_size)
{
    const int tx  = threadIdx.x;
    const int bid = blockIdx.x;

    const int q0     = bid * QPB;
    const int nq_blk = (NQ - q0 < QPB) ? (NQ - q0) : QPB;

    unsigned my_gen = 0;
    if (tx == 0) my_gen = ld_acquire_gpu(&g_bar_gen);

    // scan-state (phases 1-3) unioned with phase-5 staging (disjoint in time)
    __shared__ union {
        struct { int4 dst4[QPB + 1]; unsigned bms[BM_WORDS + 1]; } scan;
        struct { int dsl[ESTG]; int ssl[ESTG]; } e2;
    } shu;
    __shared__ int   sh_e1[CAPE1];
    __shared__ float sh_h[H_DIM];
    __shared__ float sh_p[NT];
    __shared__ float s_hid[LIN_DIM];
    __shared__ float s_mx, s_sum;

    // ---------- phase 1: load slice -> SMEM (2 quads/thread); dst==0 -> S1/E1 ----------
    if (bid == 0 && tx < H_DIM) g_root[tx] = 0.f;
#pragma unroll
    for (int half = 0; half < 2; half++) {
        int li = tx + half * NT;
        if (li < nq_blk) {
            int qi = q0 + li;
            const int4 d4 = reinterpret_cast<const int4*>(dst)[qi];
            shu.scan.dst4[li] = d4;
            int dv[4] = {d4.x, d4.y, d4.z, d4.w};
#pragma unroll
            for (int k = 0; k < 4; k++) {
                if (dv[k] == 0) {
                    int s = src[4 * qi + k];
                    int p = atomicAdd(&g_ne1, 1);
                    if (p < CAPE1) g_e1_src[p] = s;
                    if (atomicCAS(&g_slot1[s], 0, -1) == 0) {
                        int sl = atomicAdd(&g_n1, 1);
                        if (sl < CAP1) g_s1_nodes[sl] = s;
                        g_slot1[s] = sl + 1;
                        atomicOr(&g_bm1[s >> 5], 1u << (s & 31));
                    }
                }
            }
        }
    }
    GRID_SYNC();

    // ---------- phase 2: dst in S1 (SMEM bm1) -> S2 / E2 ----------
    {
        for (int i = tx; i <= BM_WORDS; i += NT) shu.scan.bms[i] = g_bm1[i];
        __syncthreads();
#pragma unroll
        for (int half = 0; half < 2; half++) {
            int li = tx + half * NT;
            if (li < nq_blk) {
                int qi = q0 + li;
                const int4 d4 = shu.scan.dst4[li];
                int dv[4] = {d4.x, d4.y, d4.z, d4.w};
#pragma unroll
                for (int k = 0; k < 4; k++) {
                    int d = dv[k];
                    if (shu.scan.bms[d >> 5] & (1u << (d & 31))) {
                        int sl = g_slot1[d] - 1;
                        if (sl >= 0 && sl < CAP1) {
                            int s = src[4 * qi + k];
                            int p = atomicAdd(&g_ne2, 1);
                            if (p < CAPE2) { g_e2_src[p] = s; g_e2_dslot[p] = sl; }
                            if (atomicCAS(&g_slot2[s], 0, -1) == 0) {
                                int q = atomicAdd(&g_n2, 1);
                                if (q < CAP2) g_s2_nodes[q] = s;
                                g_slot2[s] = q + 1;
                                atomicOr(&g_bm2[s >> 5], 1u << (s & 31));
                            }
                        }
                    }
                }
            }
        }
    }
    GRID_SYNC();

    // ---------- phase 3: dst in S2 (SMEM bm2) -> S[slot][cls[src]] += norm[src] ----------
    {
        for (int i = tx; i <= BM_WORDS; i += NT) shu.scan.bms[i] = g_bm2[i];
        __syncthreads();
#pragma unroll
        for (int half = 0; half < 2; half++) {
            int li = tx + half * NT;
            if (li < nq_blk) {
                int qi = q0 + li;
                const int4 d4 = shu.scan.dst4[li];
                int dv[4] = {d4.x, d4.y, d4.z, d4.w};
#pragma unroll
                for (int k = 0; k < 4; k++) {
                    int d = dv[k];
                    if (shu.scan.bms[d >> 5] & (1u << (d & 31))) {
                        int sl = g_slot2[d] - 1;
                        if (sl >= 0 && sl < CAP2) {
                            int s = src[4 * qi + k];
                            atomicAdd(&g_S[sl * NUM_RELS + cls[s]], norm[s]);
                        }
                    }
                }
            }
        }
    }
    GRID_SYNC();

    // ---------- phase 4: msg1 for S2 nodes ----------
    {
        int n2v = *(volatile int*)&g_n2; if (n2v > CAP2) n2v = CAP2;
        const int j = tx & (H_DIM - 1), q = tx >> 7;
        for (int sl = bid; sl < n2v; sl += NB) {
            if (tx < H_DIM) {
                const float* Sv = &g_S[sl * NUM_RELS];
                float h = 0.f;
#pragma unroll
                for (int r = 0; r < NUM_RELS; r++)
                    h = fmaf(Sv[r], W0[(r * NUM_RELS + r) * H_DIM + tx], h);
                sh_h[tx] = fmaxf(h, 0.f);
            }
            __syncthreads();
            int node = g_s2_nodes[sl];
            int c = cls[node];
            float nm = norm[node];
            const float* Wc = W1 + c * H_DIM * H_DIM;
            float p = 0.f;
#pragma unroll
            for (int kk = 0; kk < KS; kk++) {
                int k = q * KS + kk;
                p = fmaf(sh_h[k], Wc[k * H_DIM + j], p);
            }
            sh_p[tx] = p;
            __syncthreads();
            if (tx < H_DIM) {
                float a = 0.f;
#pragma unroll
                for (int g = 0; g < GRP; g++) a += sh_p[tx + g * H_DIM];
                g_msg1[sl * H_DIM + tx] = a * nm;
            }
            __syncthreads();
        }
    }
    GRID_SYNC();

    // ---------- phase 5: msg2 for S1 nodes + root accumulation ----------
    {
        int n1v = *(volatile int*)&g_n1;  if (n1v > CAP1)  n1v = CAP1;
        int ne2 = *(volatile int*)&g_ne2; if (ne2 > CAPE2) ne2 = CAPE2;
        int ne1 = *(volatile int*)&g_ne1; if (ne1 > CAPE1) ne1 = CAPE1;
        if (bid < n1v) {
            int nst = ne2 < ESTG ? ne2 : ESTG;
            for (int e = tx; e < nst; e += NT) {
                shu.e2.dsl[e] = g_e2_dslot[e];
                shu.e2.ssl[e] = g_slot2[g_e2_src[e]] - 1;
            }
            for (int i = tx; i < ne1; i += NT) sh_e1[i] = g_e1_src[i];
            __syncthreads();
            const int j = tx & (H_DIM - 1), q = tx >> 7;
            for (int sl = bid; sl < n1v; sl += NB) {
                if (tx < H_DIM) {
                    float acc = 0.f;
                    for (int e = 0; e < nst; e++) {
                        if (shu.e2.dsl[e] == sl) {
                            int ssl = shu.e2.ssl[e];
                            if (ssl >= 0 && ssl < CAP2) acc += g_msg1[ssl * H_DIM + tx];
                        }
                    }
                    for (int e = nst; e < ne2; e++) {
                        if (g_e2_dslot[e] == sl) {
                            int ssl = g_slot2[g_e2_src[e]] - 1;
                            if (ssl >= 0 && ssl < CAP2) acc += g_msg1[ssl * H_DIM + tx];
                        }
                    }
                    sh_h[tx] = fmaxf(acc, 0.f);
                }
                __syncthreads();
                int node = g_s1_nodes[sl];
                int c = cls[node];
                float nm = norm[node];
                const float* Wc = W2 + c * H_DIM * H_DIM;
                float p = 0.f;
#pragma unroll
                for (int kk = 0; kk < KS; kk++) {
                    int k = q * KS + kk;
                    p = fmaf(sh_h[k], Wc[k * H_DIM + j], p);
                }
                sh_p[tx] = p;
                __syncthreads();
                if (tx < H_DIM) {
                    float a = 0.f;
#pragma unroll
                    for (int g = 0; g < GRP; g++) a += sh_p[tx + g * H_DIM];
                    a *= nm;
                    int mult = 0;
                    for (int i = 0; i < ne1; i++) mult += (sh_e1[i] == node);
                    if (mult > 0) atomicAdd(&g_root[tx], a * (float)mult);
                }
                __syncthreads();
            }
        }
    }

    // ---------- last barrier: arrive (release); only blocks 0..3 wait ----------
    __syncthreads();
    if (tx == 0) {
        if (atom_add_release_gpu(&g_bar_cnt, 1u) == (unsigned)(NB - 1)) {
            *(volatile unsigned*)&g_bar_cnt = 0u;
            st_release_gpu(&g_bar_gen, my_gen + 1u);
        } else if (bid < 4) {
            int spin = 0;
            while (ld_acquire_gpu(&g_bar_gen) == my_gen)
                if (++spin > 64) __nanosleep(32);
        }
        my_gen++;
    }
    __syncthreads();
    if (bid >= 4) return;

    // ---------- epilogue: blocks 2/3 clean state; blocks 0/1 do heads ----------
    if (bid == 2) {
        int n1v = g_n1; if (n1v > CAP1) n1v = CAP1;
        for (int i = tx; i < n1v; i += NT) {
            int s = g_s1_nodes[i];
            g_slot1[s] = 0;
            g_bm1[s >> 5] = 0u;
        }
        __syncthreads();
        if (tx == 0) { g_n1 = 0; g_ne1 = 0; }
        return;
    }
    if (bid == 3) {
        int n2v = g_n2; if (n2v > CAP2) n2v = CAP2;
        for (int i = tx; i < n2v * NUM_RELS; i += NT) g_S[i] = 0.f;
        for (int i = tx; i < n2v; i += NT) {
            int s = g_s2_nodes[i];
            g_slot2[s] = 0;
            g_bm2[s >> 5] = 0u;
        }
        __syncthreads();
        if (tx == 0) { g_n2 = 0; g_ne2 = 0; }
        return;
    }

    // blocks 0 (actor) and 1 (critic): softmax(root) locally, then head
    {
        const int t = tx;
        const int lane = t & 31;
        const int wid  = t >> 5;
        if (t < H_DIM) sh_h[t] = g_root[t];
        __syncthreads();
        if (wid == 0) {
            float m = fmaxf(fmaxf(sh_h[lane], sh_h[lane + 32]),
                            fmaxf(sh_h[lane + 64], sh_h[lane + 96]));
            m = warp_max_f(m);
            if (lane == 0) s_mx = m;
        }
        __syncthreads();
        if (t < H_DIM) sh_h[t] = expf(sh_h[t] - s_mx);
        __syncthreads();
        if (wid == 0) {
            float sm = sh_h[lane] + sh_h[lane + 32] + sh_h[lane + 64] + sh_h[lane + 96];
            sm = warp_sum_f(sm);
            if (lane == 0) s_sum = sm;
        }
        __syncthreads();
        if (t < H_DIM) sh_h[t] *= (1.f / s_sum);
        __syncthreads();

        if (bid == 0) {
            if (t < LIN_DIM) {
                float a = a1_b[t];
#pragma unroll 8
                for (int k = 0; k < H_DIM; k++) a = fmaf(sh_h[k], a1_w[k * LIN_DIM + t], a);
                s_hid[t] = fmaxf(a, 0.f);
            }
            __syncthreads();
            if (t < LIN_DIM) {
                int q = t >> 7, j = t & 127;
                const int k0 = q * 128;
                float p = 0.f;
#pragma unroll 8
                for (int k = 0; k < 128; k++)
                    p = fmaf(s_hid[k0 + k], a2_w[(k0 + k) * H_DIM + j], p);
                sh_p[t] = p;
            }
            __syncthreads();
            if (t < H_DIM)
                out[t] = a2_b[t] + sh_p[t] + sh_p[t + 128] + sh_p[t + 256] + sh_p[t + 384];
        } else {
            if (t < LIN_DIM) {
                float a = c1_b[t];
#pragma unroll 8
                for (int k = 0; k < H_DIM; k++) a = fmaf(sh_h[k], c1_w[k * LIN_DIM + t], a);
                s_hid[t] = fmaxf(a, 0.f);
            }
            __syncthreads();
            if (t < LIN_DIM) {
                float p = warp_sum_f(s_hid[t] * c2_w[t]);
                if (lane == 0) sh_p[wid] = p;
            }
            __syncthreads();
            if (t == 0) {
                float a = c2_b[0];
#pragma unroll
                for (int i = 0; i < 16; i++) a += sh_p[i];
                if (out_size > H_DIM) out[H_DIM] = a;
            }
        }
    }
}

// ---------------- launch ----------------
extern "C" void kernel_launch(void* const* d_in, const int* in_sizes, int n_in,
                              void* d_out, int out_size) {
    const int*   cls  = (const int*)  d_in[0];
    const float* norm = (const float*)d_in[1];
    const int*   src  = (const int*)  d_in[2];
    const int*   dst  = (const int*)  d_in[3];
    const float* W0   = (const float*)d_in[4];
    const float* W1   = (const float*)d_in[5];
    const float* W2   = (const float*)d_in[6];
    const float* a1_w = (const float*)d_in[7];
    const float* a1_b = (const float*)d_in[8];
    const float* a2_w = (const float*)d_in[9];
    const float* a2_b = (const float*)d_in[10];
    const float* c1_w = (const float*)d_in[11];
    const float* c1_b = (const float*)d_in[12];
    const float* c2_w = (const float*)d_in[13];
    const float* c2_b = (const float*)d_in[14];
    float* out = (float*)d_out;

    k_fused<<<NB, NT>>>(cls, norm, src, dst, W0, W1, W2,
                        a1_w, a1_b, a2_w, a2_b, c1_w, c1_b, c2_w, c2_b,
                        out, out_size);
}

// round 11
// speedup vs baseline: 1.2732x; 1.1694x over previous
#include <cuda_runtime.h>
#include <math.h>

#define N_NODES 50000
#define N_EDGES 800000
#define NUM_RELS 16
#define H_DIM 128
#define LIN_DIM 512

#define CAP1 256
#define CAPE1 512
#define CAPE2 4096

#define BM_WORDS ((N_NODES + 31) / 32)   // 1563

#define NB 148                 // 1 block/SM
#define NT 1024                // 32 warps/SM
#define NQ (N_EDGES / 4)       // 200000 int4 quads
#define QPB ((NQ + NB - 1) / NB)     // 1352 quads per block
#define GRP (NT / H_DIM)       // 8 k-groups for GEMV
#define KS  (H_DIM / GRP)      // 16 k's per group

#define NSALL  (N_NODES * NUM_RELS)      // 800000 floats
#define NSALL4 (NSALL / 4)               // 200000 float4
#define SPB    ((NSALL4 + NB - 1) / NB)  // 1352 float4 per block

// -------- scratch (device globals; zero-init valid; cleared per-launch in phase 1) --------
__device__ int          g_slot1[N_NODES];       // 0 = absent, slot+1
__device__ unsigned int g_bm1[BM_WORDS + 1];
__device__ int    g_n1, g_ne1, g_ne2;
__device__ int    g_s1_nodes[CAP1];
__device__ int    g_e1_src[CAPE1];
__device__ int    g_e2_src[CAPE2];
__device__ int    g_e2_dslot[CAPE2];
__device__ float2 g_cn[N_NODES];                // {norm, as_float(cls)}  (repacked each launch)
__device__ float  g_Sall[NSALL];                // per-(node, rel) sums   (cleared in phase 1)
__device__ float  g_h2[CAP1 * H_DIM];           // layer-2 pre-act        (cleared in phase 1)
__device__ float  g_root[H_DIM];                // node-0 layer-3 pre-act (cleared in phase 1)

// persistent-generation grid barrier
__device__ unsigned g_bar_cnt;
__device__ unsigned g_bar_gen;

__device__ __forceinline__ unsigned atom_add_release_gpu(unsigned* p, unsigned v) {
    unsigned old;
    asm volatile("atom.add.release.gpu.u32 %0, [%1], %2;"
                 : "=r"(old) : "l"(p), "r"(v) : "memory");
    return old;
}
__device__ __forceinline__ unsigned ld_acquire_gpu(unsigned* p) {
    unsigned v;
    asm volatile("ld.acquire.gpu.u32 %0, [%1];" : "=r"(v) : "l"(p) : "memory");
    return v;
}
__device__ __forceinline__ void st_release_gpu(unsigned* p, unsigned v) {
    asm volatile("st.release.gpu.u32 [%0], %1;" :: "l"(p), "r"(v) : "memory");
}

#define GRID_SYNC()                                                          \
    do {                                                                     \
        __syncthreads();                                                     \
        if (threadIdx.x == 0) {                                              \
            if (atom_add_release_gpu(&g_bar_cnt, 1u) == (unsigned)(NB - 1)) {\
                *(volatile unsigned*)&g_bar_cnt = 0u;                        \
                st_release_gpu(&g_bar_gen, my_gen + 1u);                     \
            } else {                                                         \
                int spin = 0;                                                \
                while (ld_acquire_gpu(&g_bar_gen) == my_gen)                 \
                    if (++spin > 64) __nanosleep(32);                        \
            }                                                                \
            my_gen++;                                                        \
        }                                                                    \
        __syncthreads();                                                     \
    } while (0)

__device__ __forceinline__ float warp_max_f(float v) {
#pragma unroll
    for (int o = 16; o > 0; o >>= 1) v = fmaxf(v, __shfl_down_sync(0xffffffffu, v, o));
    return v;
}
__device__ __forceinline__ float warp_sum_f(float v) {
#pragma unroll
    for (int o = 16; o > 0; o >>= 1) v += __shfl_down_sync(0xffffffffu, v, o);
    return v;
}

__global__ void __launch_bounds__(NT, 1) k_fused(
    const int* __restrict__ cls, const float* __restrict__ norm,
    const int* __restrict__ src, const int* __restrict__ dst,
    const float* __restrict__ W0, const float* __restrict__ W1,
    const float* __restrict__ W2,
    const float* __restrict__ a1_w, const float* __restrict__ a1_b,
    const float* __restrict__ a2_w, const float* __restrict__ a2_b,
    const float* __restrict__ c1_w, const float* __restrict__ c1_b,
    const float* __restrict__ c2_w, const float* __restrict__ c2_b,
    float* __restrict__ out, int out_size)
{
    const int tx  = threadIdx.x;
    const int bid = blockIdx.x;
    const int gt  = bid * NT + tx;

    const int q0     = bid * QPB;
    const int nq_blk = (NQ - q0 < QPB) ? (NQ - q0) : QPB;

    unsigned my_gen = 0;
    if (tx == 0) my_gen = ld_acquire_gpu(&g_bar_gen);

    __shared__ int4     sh_dst4[QPB + 1];          // 21.6 KB
    __shared__ unsigned sh_bm[BM_WORDS + 1];       // 6.3 KB
    __shared__ int      sh_e1[CAPE1];              // 2 KB
    __shared__ float    sh_h[H_DIM];
    __shared__ float    sh_p[NT];                  // 4 KB
    __shared__ float    s_hid[LIN_DIM];            // 2 KB
    __shared__ float    s_mx, s_sum;

    // ========== phase 1: pack cn; clear S_all/h2/root; scan dst==0 -> S1/E1 ==========
    {
        // pack (norm, cls) -> float2 (coalesced; grid covers 50k in one shot)
        if (gt < N_NODES)
            g_cn[gt] = make_float2(norm[gt], __int_as_float(cls[gt]));

        // clear this block's S_all slice
        {
            const float4 z4 = make_float4(0.f, 0.f, 0.f, 0.f);
            int s0 = bid * SPB;
            int sn = NSALL4 - s0; if (sn > SPB) sn = SPB;
            for (int i = tx; i < sn; i += NT)
                reinterpret_cast<float4*>(g_Sall)[s0 + i] = z4;
        }
        // clear h2 (block 1) and root (block 0)
        if (bid == 1) {
            const float4 z4 = make_float4(0.f, 0.f, 0.f, 0.f);
            for (int i = tx; i < (CAP1 * H_DIM) / 4; i += NT)
                reinterpret_cast<float4*>(g_h2)[i] = z4;
        }
        if (bid == 0 && tx < H_DIM) g_root[tx] = 0.f;

        // scan slice (cache dst quads in SMEM); dst==0 -> E1 / S1
#pragma unroll
        for (int half = 0; half < 2; half++) {
            int li = tx + half * NT;
            if (li < nq_blk) {
                int qi = q0 + li;
                const int4 d4 = reinterpret_cast<const int4*>(dst)[qi];
                sh_dst4[li] = d4;
                int dv[4] = {d4.x, d4.y, d4.z, d4.w};
#pragma unroll
                for (int k = 0; k < 4; k++) {
                    if (dv[k] == 0) {
                        int s = src[4 * qi + k];
                        int p = atomicAdd(&g_ne1, 1);
                        if (p < CAPE1) g_e1_src[p] = s;
                        if (atomicCAS(&g_slot1[s], 0, -1) == 0) {
                            int sl = atomicAdd(&g_n1, 1);
                            if (sl < CAP1) g_s1_nodes[sl] = s;
                            g_slot1[s] = sl + 1;
                            atomicOr(&g_bm1[s >> 5], 1u << (s & 31));
                        }
                    }
                }
            }
        }
    }
    GRID_SYNC();

    // ========== phase 2: full scan: S_all RED + (dst in S1 -> E2) ==========
    {
        for (int i = tx; i <= BM_WORDS; i += NT) sh_bm[i] = g_bm1[i];
        __syncthreads();
#pragma unroll
        for (int half = 0; half < 2; half++) {
            int li = tx + half * NT;
            if (li < nq_blk) {
                int qi = q0 + li;
                const int4 d4 = sh_dst4[li];
                const int4 s4 = reinterpret_cast<const int4*>(src)[qi];
                int dv[4] = {d4.x, d4.y, d4.z, d4.w};
                int sv[4] = {s4.x, s4.y, s4.z, s4.w};
#pragma unroll
                for (int k = 0; k < 4; k++) {
                    int d = dv[k], s = sv[k];
                    float2 cn = g_cn[s];
                    int c = __float_as_int(cn.y);
                    atomicAdd(&g_Sall[d * NUM_RELS + c], cn.x);   // RED, no return
                    if (sh_bm[d >> 5] & (1u << (d & 31))) {
                        int sl = g_slot1[d] - 1;
                        if (sl >= 0 && sl < CAP1) {
                            int p = atomicAdd(&g_ne2, 1);
                            if (p < CAPE2) { g_e2_src[p] = s; g_e2_dslot[p] = sl; }
                        }
                    }
                }
            }
        }
    }
    GRID_SYNC();

    // ========== phase 3: per-E2-edge msg1 on the fly -> h2[dslot] ==========
    // h1 = relu(S_all[s] . T0); msg1 = (h1 @ W1[cls[s]]) * norm[s]; h2[dsl] += msg1
    {
        int ne2 = *(volatile int*)&g_ne2; if (ne2 > CAPE2) ne2 = CAPE2;
        const int j = tx & (H_DIM - 1), q = tx >> 7;
        for (int e = bid; e < ne2; e += NB) {
            int s   = g_e2_src[e];
            int dsl = g_e2_dslot[e];
            if (tx < H_DIM) {
                const float* Sv = &g_Sall[s * NUM_RELS];
                float h = 0.f;
#pragma unroll
                for (int r = 0; r < NUM_RELS; r++)
                    h = fmaf(Sv[r], W0[(r * NUM_RELS + r) * H_DIM + tx], h);
                sh_h[tx] = fmaxf(h, 0.f);
            }
            __syncthreads();
            float2 cn = g_cn[s];
            int c = __float_as_int(cn.y);
            const float* Wc = W1 + c * H_DIM * H_DIM;
            float p = 0.f;
#pragma unroll
            for (int kk = 0; kk < KS; kk++) {
                int k = q * KS + kk;
                p = fmaf(sh_h[k], Wc[k * H_DIM + j], p);
            }
            sh_p[tx] = p;
            __syncthreads();
            if (tx < H_DIM && dsl >= 0 && dsl < CAP1) {
                float a = 0.f;
#pragma unroll
                for (int g = 0; g < GRP; g++) a += sh_p[tx + g * H_DIM];
                atomicAdd(&g_h2[dsl * H_DIM + tx], a * cn.x);
            }
            __syncthreads();
        }
    }
    GRID_SYNC();

    // ========== phase 4: msg2 for S1 nodes + root accumulation ==========
    {
        int n1v = *(volatile int*)&g_n1; if (n1v > CAP1)  n1v = CAP1;
        int ne1 = *(volatile int*)&g_ne1; if (ne1 > CAPE1) ne1 = CAPE1;
        if (bid < n1v) {
            for (int i = tx; i < ne1; i += NT) sh_e1[i] = g_e1_src[i];
            __syncthreads();
            const int j = tx & (H_DIM - 1), q = tx >> 7;
            for (int sl = bid; sl < n1v; sl += NB) {
                if (tx < H_DIM) sh_h[tx] = fmaxf(g_h2[sl * H_DIM + tx], 0.f);
                __syncthreads();
                int node = g_s1_nodes[sl];
                float2 cn = g_cn[node];
                int c = __float_as_int(cn.y);
                const float* Wc = W2 + c * H_DIM * H_DIM;
                float p = 0.f;
#pragma unroll
                for (int kk = 0; kk < KS; kk++) {
                    int k = q * KS + kk;
                    p = fmaf(sh_h[k], Wc[k * H_DIM + j], p);
                }
                sh_p[tx] = p;
                __syncthreads();
                if (tx < H_DIM) {
                    float a = 0.f;
#pragma unroll
                    for (int g = 0; g < GRP; g++) a += sh_p[tx + g * H_DIM];
                    a *= cn.x;
                    int mult = 0;
                    for (int i = 0; i < ne1; i++) mult += (sh_e1[i] == node);
                    if (mult > 0) atomicAdd(&g_root[tx], a * (float)mult);
                }
                __syncthreads();
            }
        }
    }

    // ========== last barrier: arrive (release); only blocks 0..2 wait ==========
    __syncthreads();
    if (tx == 0) {
        if (atom_add_release_gpu(&g_bar_cnt, 1u) == (unsigned)(NB - 1)) {
            *(volatile unsigned*)&g_bar_cnt = 0u;
            st_release_gpu(&g_bar_gen, my_gen + 1u);
        } else if (bid < 3) {
            int spin = 0;
            while (ld_acquire_gpu(&g_bar_gen) == my_gen)
                if (++spin > 64) __nanosleep(32);
        }
        my_gen++;
    }
    __syncthreads();
    if (bid >= 3) return;

    // ========== epilogue: block 2 cleans S1 state; blocks 0/1 do heads ==========
    if (bid == 2) {
        int n1v = g_n1; if (n1v > CAP1) n1v = CAP1;
        for (int i = tx; i < n1v; i += NT) {
            int s = g_s1_nodes[i];
            g_slot1[s] = 0;
            g_bm1[s >> 5] = 0u;
        }
        __syncthreads();
        if (tx == 0) { g_n1 = 0; g_ne1 = 0; g_ne2 = 0; }
        return;
    }

    // blocks 0 (actor) and 1 (critic): softmax(root) locally, then head
    {
        const int t = tx;
        const int lane = t & 31;
        const int wid  = t >> 5;
        if (t < H_DIM) sh_h[t] = g_root[t];
        __syncthreads();
        if (wid == 0) {
            float m = fmaxf(fmaxf(sh_h[lane], sh_h[lane + 32]),
                            fmaxf(sh_h[lane + 64], sh_h[lane + 96]));
            m = warp_max_f(m);
            if (lane == 0) s_mx = m;
        }
        __syncthreads();
        if (t < H_DIM) sh_h[t] = expf(sh_h[t] - s_mx);
        __syncthreads();
        if (wid == 0) {
            float sm = sh_h[lane] + sh_h[lane + 32] + sh_h[lane + 64] + sh_h[lane + 96];
            sm = warp_sum_f(sm);
            if (lane == 0) s_sum = sm;
        }
        __syncthreads();
        if (t < H_DIM) sh_h[t] *= (1.f / s_sum);
        __syncthreads();

        if (bid == 0) {
            if (t < LIN_DIM) {
                float a = a1_b[t];
#pragma unroll 8
                for (int k = 0; k < H_DIM; k++) a = fmaf(sh_h[k], a1_w[k * LIN_DIM + t], a);
                s_hid[t] = fmaxf(a, 0.f);
            }
            __syncthreads();
            if (t < LIN_DIM) {
                int q = t >> 7, j = t & 127;
                const int k0 = q * 128;
                float p = 0.f;
#pragma unroll 8
                for (int k = 0; k < 128; k++)
                    p = fmaf(s_hid[k0 + k], a2_w[(k0 + k) * H_DIM + j], p);
                sh_p[t] = p;
            }
            __syncthreads();
            if (t < H_DIM)
                out[t] = a2_b[t] + sh_p[t] + sh_p[t + 128] + sh_p[t + 256] + sh_p[t + 384];
        } else {
            if (t < LIN_DIM) {
                float a = c1_b[t];
#pragma unroll 8
                for (int k = 0; k < H_DIM; k++) a = fmaf(sh_h[k], c1_w[k * LIN_DIM + t], a);
                s_hid[t] = fmaxf(a, 0.f);
            }
            __syncthreads();
            if (t < LIN_DIM) {
                float p = warp_sum_f(s_hid[t] * c2_w[t]);
                if (lane == 0) sh_p[wid] = p;
            }
            __syncthreads();
            if (t == 0) {
                float a = c2_b[0];
#pragma unroll
                for (int i = 0; i < 16; i++) a += sh_p[i];
                if (out_size > H_DIM) out[H_DIM] = a;
            }
        }
    }
}

// ---------------- launch ----------------
extern "C" void kernel_launch(void* const* d_in, const int* in_sizes, int n_in,
                              void* d_out, int out_size) {
    const int*   cls  = (const int*)  d_in[0];
    const float* norm = (const float*)d_in[1];
    const int*   src  = (const int*)  d_in[2];
    const int*   dst  = (const int*)  d_in[3];
    const float* W0   = (const float*)d_in[4];
    const float* W1   = (const float*)d_in[5];
    const float* W2   = (const float*)d_in[6];
    const float* a1_w = (const float*)d_in[7];
    const float* a1_b = (const float*)d_in[8];
    const float* a2_w = (const float*)d_in[9];
    const float* a2_b = (const float*)d_in[10];
    const float* c1_w = (const float*)d_in[11];
    const float* c1_b = (const float*)d_in[12];
    const float* c2_w = (const float*)d_in[13];
    const float* c2_b = (const float*)d_in[14];
    float* out = (float*)d_out;

    k_fused<<<NB, NT>>>(cls, norm, src, dst, W0, W1, W2,
                        a1_w, a1_b, a2_w, a2_b, c1_w, c1_b, c2_w, c2_b,
                        out, out_size);
}